// round 7
// baseline (speedup 1.0000x reference)
#include <cuda_runtime.h>
#include <math.h>
#include <stdint.h>

#define BB 4
#define NN 4096
#define FF 512
#define HA 128
#define HV 32

// Scratch (device globals: no allocation allowed)
__device__ float g_hn[BB][NN][HA];    // normalized h, row-major, tf32-rounded (8 MB)
__device__ float g_part[BB][32];

// ---------------------------------------------------------------------------
__device__ __forceinline__ float tf32r(float x) {
    uint32_t o;
    asm("cvt.rna.tf32.f32 %0, %1;" : "=r"(o) : "f"(x));
    return __uint_as_float(o);
}

__device__ __forceinline__ uint32_t s2u(const void* p) {
    uint32_t a;
    asm("{ .reg .u64 t; cvta.to.shared.u64 t, %1; cvt.u32.u64 %0, t; }"
        : "=r"(a) : "l"(p));
    return a;
}

__device__ __forceinline__ void cp16(uint32_t dst, const float* src) {
    asm volatile("cp.async.cg.shared.global [%0], [%1], 16;"
                 :: "r"(dst), "l"(src));
}

__device__ __forceinline__ void mma_tf32(float* d, const uint32_t* a,
                                         const uint32_t* b) {
    asm volatile(
        "mma.sync.aligned.m16n8k8.row.col.f32.tf32.tf32.f32 "
        "{%0,%1,%2,%3}, {%4,%5,%6,%7}, {%8,%9}, {%0,%1,%2,%3};"
        : "+f"(d[0]), "+f"(d[1]), "+f"(d[2]), "+f"(d[3])
        : "r"(a[0]), "r"(a[1]), "r"(a[2]), "r"(a[3]), "r"(b[0]), "r"(b[1]));
}

// ---------------------------------------------------------------------------
// FUSED hc kernel (unchanged, proven 32us).
// ---------------------------------------------------------------------------
#define AS0 0
#define AS1 4608            // As: [128][36]
#define BS0 9216
#define BS1 13568           // Bs: [32][136]
#define WS0 17920
#define WS1 19200           // Ws: [32][40]
#define REDO 20480          // [128][8]
#define RINVO 21504         // [128]
#define CREDO 21632         // [128]
#define CWO 21760           // [4]
#define HC_FLOATS 21764
#define HC_SMEM_BYTES (HC_FLOATS * 4)

__global__ __launch_bounds__(256, 1) void hc_kernel(const float* __restrict__ obs,
                                                    const float* __restrict__ gen_number,
                                                    const float* __restrict__ W_gen,
                                                    const float* __restrict__ b_gen,
                                                    const float* __restrict__ W_act,
                                                    const float* __restrict__ b_act,
                                                    const float* __restrict__ W_v1,
                                                    const float* __restrict__ b_v1,
                                                    const float* __restrict__ W_v2,
                                                    const float* __restrict__ b_v2) {
    extern __shared__ float sm[];
    const uint32_t smb = s2u(sm);

    const int b  = blockIdx.y;
    const int m0 = blockIdx.x * 128;
    const int tid = threadIdx.x;
    const int wid = tid >> 5;
    const int lane = tid & 31;
    const int g = lane >> 2;
    const int t = lane & 3;
    const int wm = wid >> 1;
    const int wn = wid & 1;

    const float* obs_b = obs + ((size_t)b * NN + m0) * FF;

    float acc[2][8][4];
    float accv[2][4][4];
#pragma unroll
    for (int mi = 0; mi < 2; mi++) {
#pragma unroll
        for (int ni = 0; ni < 8; ni++)
#pragma unroll
            for (int q = 0; q < 4; q++) acc[mi][ni][q] = 0.f;
#pragma unroll
        for (int ni = 0; ni < 4; ni++)
#pragma unroll
            for (int q = 0; q < 4; q++) accv[mi][ni][q] = 0.f;
    }

    auto issue = [&](int ck, int buf) {
        const int k0 = ck * 32;
        uint32_t as = smb + (uint32_t)((buf ? AS1 : AS0) * 4);
        uint32_t bs = smb + (uint32_t)((buf ? BS1 : BS0) * 4);
        uint32_t ws = smb + (uint32_t)((buf ? WS1 : WS0) * 4);
#pragma unroll
        for (int i = 0; i < 4; i++) {
            int c = tid + i * 256;
            int row = c >> 3, kc = c & 7;
            cp16(as + (uint32_t)(row * 36 + kc * 4) * 4u,
                 obs_b + (size_t)row * FF + k0 + kc * 4);
        }
#pragma unroll
        for (int i = 0; i < 4; i++) {
            int c = tid + i * 256;
            int kk = c >> 5, cg = c & 31;
            cp16(bs + (uint32_t)(kk * 136 + cg * 4) * 4u,
                 W_act + (size_t)(k0 + kk) * HA + cg * 4);
        }
        {
            int kk = tid >> 3, cg = tid & 7;
            cp16(ws + (uint32_t)(kk * 40 + cg * 4) * 4u,
                 W_v1 + (size_t)(k0 + kk) * HV + cg * 4);
        }
    };

    issue(0, 0);
    asm volatile("cp.async.commit_group;" ::: "memory");
    issue(1, 1);
    asm volatile("cp.async.commit_group;" ::: "memory");
    asm volatile("cp.async.wait_group 1;" ::: "memory");
    __syncthreads();

#pragma unroll 1
    for (int ck = 0; ck < 16; ck++) {
        const int buf = ck & 1;
        const float* A  = sm + (buf ? AS1 : AS0) + wm * 32 * 36;
        const float* Bm = sm + (buf ? BS1 : BS0) + wn * 64;
        const float* Wc = sm + (buf ? WS1 : WS0);
#pragma unroll
        for (int ks = 0; ks < 4; ks++) {
            const int kk = ks * 8;
            uint32_t af[2][4];
#pragma unroll
            for (int mi = 0; mi < 2; mi++) {
                const float* ap = A + (mi * 16 + g) * 36 + kk + t;
                af[mi][0] = __float_as_uint(ap[0]);
                af[mi][1] = __float_as_uint(ap[8 * 36]);
                af[mi][2] = __float_as_uint(ap[4]);
                af[mi][3] = __float_as_uint(ap[8 * 36 + 4]);
            }
            uint32_t bf[8][2];
#pragma unroll
            for (int ni = 0; ni < 8; ni++) {
                const float* bp = Bm + (kk + t) * 136 + ni * 8 + g;
                bf[ni][0] = __float_as_uint(bp[0]);
                bf[ni][1] = __float_as_uint(bp[4 * 136]);
            }
#pragma unroll
            for (int mi = 0; mi < 2; mi++)
#pragma unroll
                for (int ni = 0; ni < 8; ni++)
                    mma_tf32(acc[mi][ni], af[mi], bf[ni]);
            if (wn == 0) {
                uint32_t bc[4][2];
#pragma unroll
                for (int ni = 0; ni < 4; ni++) {
                    const float* bp = Wc + (kk + t) * 40 + ni * 8 + g;
                    bc[ni][0] = __float_as_uint(bp[0]);
                    bc[ni][1] = __float_as_uint(bp[4 * 40]);
                }
#pragma unroll
                for (int mi = 0; mi < 2; mi++)
#pragma unroll
                    for (int ni = 0; ni < 4; ni++)
                        mma_tf32(accv[mi][ni], af[mi], bc[ni]);
            }
        }
        __syncthreads();
        if (ck + 2 < 16) issue(ck + 2, buf);
        asm volatile("cp.async.commit_group;" ::: "memory");
        asm volatile("cp.async.wait_group 1;" ::: "memory");
        __syncthreads();
    }

    float gv;
    {
        float x = gen_number[b] * W_gen[0] + b_gen[0];
        gv = (x > 0.f) ? x : 0.01f * x;
    }

#pragma unroll
    for (int ni = 0; ni < 8; ni++) {
        int c0 = wn * 64 + ni * 8 + 2 * t;
        float a0 = fmaf(gv, W_act[(size_t)FF * HA + c0], b_act[c0]);
        float a1 = fmaf(gv, W_act[(size_t)FF * HA + c0 + 1], b_act[c0 + 1]);
#pragma unroll
        for (int mi = 0; mi < 2; mi++) {
            acc[mi][ni][0] += a0; acc[mi][ni][1] += a1;
            acc[mi][ni][2] += a0; acc[mi][ni][3] += a1;
        }
    }

    float* RED = sm + REDO;
#pragma unroll
    for (int mi = 0; mi < 2; mi++)
#pragma unroll
        for (int d = 0; d < 2; d++) {
            float s = 0.f;
#pragma unroll
            for (int ni = 0; ni < 8; ni++) {
                s = fmaf(acc[mi][ni][2 * d], acc[mi][ni][2 * d], s);
                s = fmaf(acc[mi][ni][2 * d + 1], acc[mi][ni][2 * d + 1], s);
            }
            int row = wm * 32 + mi * 16 + g + 8 * d;
            RED[row * 8 + wn * 4 + t] = s;
        }
    __syncthreads();
    float* RINV = sm + RINVO;
    if (tid < 128) {
        float s = 0.f;
#pragma unroll
        for (int x = 0; x < 8; x++) s += RED[tid * 8 + x];
        RINV[tid] = 1.f / fmaxf(sqrtf(s), 1e-8f);
    }
    __syncthreads();

    float* STG = sm;
#pragma unroll
    for (int mi = 0; mi < 2; mi++)
#pragma unroll
        for (int d = 0; d < 2; d++) {
            int row = wm * 32 + mi * 16 + g + 8 * d;
            float iv = RINV[row];
#pragma unroll
            for (int ni = 0; ni < 8; ni++) {
                int col = wn * 64 + ni * 8 + 2 * t;
                STG[row * 132 + col]     = tf32r(acc[mi][ni][2 * d] * iv);
                STG[row * 132 + col + 1] = tf32r(acc[mi][ni][2 * d + 1] * iv);
            }
        }

    float* CRED = sm + CREDO;
    if (wn == 0) {
#pragma unroll
        for (int mi = 0; mi < 2; mi++)
#pragma unroll
            for (int d = 0; d < 2; d++) {
                float cv = 0.f;
#pragma unroll
                for (int ni = 0; ni < 4; ni++) {
#pragma unroll
                    for (int j = 0; j < 2; j++) {
                        int cc = ni * 8 + 2 * t + j;
                        float hvv = accv[mi][ni][2 * d + j] +
                                    fmaf(gv, W_v1[(size_t)FF * HV + cc], b_v1[cc]);
                        hvv = fmaxf(hvv, 0.f);
                        cv = fmaf(hvv, W_v2[cc], cv);
                    }
                }
                cv += __shfl_xor_sync(0xffffffffu, cv, 1);
                cv += __shfl_xor_sync(0xffffffffu, cv, 2);
                if (t == 0) {
                    int row = wm * 32 + mi * 16 + g + 8 * d;
                    CRED[row] = cv + b_v2[0];
                }
            }
    }
    __syncthreads();

#pragma unroll
    for (int i = 0; i < 16; i++) {
        int idx = tid + i * 256;
        int row = idx >> 5, c4 = idx & 31;
        float4 v = *(float4*)&STG[row * 132 + c4 * 4];
        *(float4*)&g_hn[b][m0 + row][c4 * 4] = v;
    }

    float* CW = sm + CWO;
    if (tid < 128) {
        float v = CRED[tid];
#pragma unroll
        for (int off = 16; off > 0; off >>= 1)
            v += __shfl_down_sync(0xffffffffu, v, off);
        if ((tid & 31) == 0) CW[tid >> 5] = v;
    }
    __syncthreads();
    if (tid == 0)
        g_part[b][blockIdx.x] = CW[0] + CW[1] + CW[2] + CW[3];
}

// ---------------------------------------------------------------------------
// Actor v4: 512 threads, CTA tile 256(m) x 128(n), warp grid 4x4, warp tile
// 64x32. A and B split in k-halves [.][68], cp.async pipelined. 16 warps ->
// 4 warps/SMSP. Symmetric per 128x128 quadrant (warp rows lie in exactly one):
// j<ih skip, j==ih direct, j>ih direct + mirror staged through free A bufs.
// ---------------------------------------------------------------------------
#define LDK 68
#define AH_WORDS (256 * LDK)             // 17408
#define BH_WORDS (128 * LDK)             // 8704
#define A0W 0
#define A1W AH_WORDS
#define B0W (2 * AH_WORDS)
#define B1W (2 * AH_WORDS + BH_WORDS)
#define ACT_WORDS (2 * AH_WORDS + 2 * BH_WORDS)   // 52224
#define ACT_SMEM_BYTES (ACT_WORDS * 4)            // 208896
#define LDT 132                                    // mirror staging stride

__global__ __launch_bounds__(512, 1) void actor_kernel(float* __restrict__ out,
                                                       int out_size) {
    extern __shared__ float smem[];
    float* A0 = smem + A0W;
    float* A1 = smem + A1W;
    float* B0 = smem + B0W;
    float* B1 = smem + B1W;

    const int tid = threadIdx.x;
    const int wid = tid >> 5;
    const int lane = tid & 31;
    const int g = lane >> 2;
    const int t = lane & 3;
    const int wm = wid >> 2;             // 0..3 (m)
    const int wn = wid & 3;              // 0..3 (n)
    const int b = blockIdx.y;
    const int cid = blockIdx.x;

    // fold critic finalize into one CTA
    if (cid == 0 && b == 0 && tid < BB) {
        float s = 0.f;
#pragma unroll
        for (int k = 0; k < 32; k++) s += g_part[tid][k];
        out[(size_t)out_size - BB + tid] = s * (1.f / NN);
    }

    // decode cid -> (ic, j) with j >= 2*ic ; ic = 256-row chunk, j = 128-col tile
    int ic = 0, j;
    {
        int c = cid, ch;
        while (c >= (ch = 32 - 2 * ic)) { c -= ch; ic++; }
        j = 2 * ic + c;
    }

    const float* hb = &g_hn[b][0][0];
    const uint32_t sA0 = s2u(A0);
    const uint32_t sA1 = s2u(A1);
    const uint32_t sB0 = s2u(B0);
    const uint32_t sB1 = s2u(B1);

    // prologue: (A half0 + B half0) group 0 ; (A half1 + B half1) group 1
    {
        const float* aSrc = hb + (size_t)(ic * 256) * HA;
        const float* bSrc = hb + (size_t)(j * 128) * HA;
#pragma unroll
        for (int it = 0; it < 8; it++) {          // A0: 256 x 16 chunks
            int c = tid + it * 512;
            int row = c >> 4, kc = c & 15;
            cp16(sA0 + (uint32_t)(row * LDK + kc * 4) * 4u,
                 aSrc + (size_t)row * HA + kc * 4);
        }
#pragma unroll
        for (int it = 0; it < 4; it++) {          // B0: 128 x 16 chunks
            int c = tid + it * 512;
            int row = c >> 4, kc = c & 15;
            cp16(sB0 + (uint32_t)(row * LDK + kc * 4) * 4u,
                 bSrc + (size_t)row * HA + kc * 4);
        }
        asm volatile("cp.async.commit_group;" ::: "memory");
#pragma unroll
        for (int it = 0; it < 8; it++) {          // A1
            int c = tid + it * 512;
            int row = c >> 4, kc = c & 15;
            cp16(sA1 + (uint32_t)(row * LDK + kc * 4) * 4u,
                 aSrc + (size_t)row * HA + 64 + kc * 4);
        }
#pragma unroll
        for (int it = 0; it < 4; it++) {          // B1
            int c = tid + it * 512;
            int row = c >> 4, kc = c & 15;
            cp16(sB1 + (uint32_t)(row * LDK + kc * 4) * 4u,
                 bSrc + (size_t)row * HA + 64 + kc * 4);
        }
        asm volatile("cp.async.commit_group;" ::: "memory");
    }
    asm volatile("cp.async.wait_group 1;" ::: "memory");
    __syncthreads();

    float acc[4][4][4];
#pragma unroll
    for (int mi = 0; mi < 4; mi++)
#pragma unroll
        for (int ni = 0; ni < 4; ni++)
#pragma unroll
            for (int q = 0; q < 4; q++) acc[mi][ni][q] = 0.f;

#pragma unroll 1
    for (int half = 0; half < 2; half++) {
        if (half == 1) {
            asm volatile("cp.async.wait_group 0;" ::: "memory");
            __syncthreads();
        }
        const float* Aw = (half ? A1 : A0) + (wm * 64) * LDK;
        const float* Bw = (half ? B1 : B0) + (wn * 32) * LDK;
#pragma unroll
        for (int ks = 0; ks < 8; ks++) {
            const int kk = ks * 8;
            uint32_t af[4][4];
#pragma unroll
            for (int mi = 0; mi < 4; mi++) {
                const float* ap = Aw + (mi * 16 + g) * LDK + kk + t;
                af[mi][0] = __float_as_uint(ap[0]);
                af[mi][1] = __float_as_uint(ap[8 * LDK]);
                af[mi][2] = __float_as_uint(ap[4]);
                af[mi][3] = __float_as_uint(ap[8 * LDK + 4]);
            }
            uint32_t bf[4][2];
#pragma unroll
            for (int ni = 0; ni < 4; ni++) {
                const float* bp = Bw + (ni * 8 + g) * LDK + kk + t;
                bf[ni][0] = __float_as_uint(bp[0]);
                bf[ni][1] = __float_as_uint(bp[4]);
            }
#pragma unroll
            for (int mi = 0; mi < 4; mi++)
#pragma unroll
                for (int ni = 0; ni < 4; ni++)
                    mma_tf32(acc[mi][ni], af[mi], bf[ni]);
        }
    }
    __syncthreads();   // all buffers now free for staging

    const int ih = 2 * ic + (wm >> 1);        // this warp's 128-row quadrant
    const bool doDirect = (j >= ih);
    const bool doMirror = (j > ih);

    // direct store: rows ic*256 + wm*64 .., cols j*128 + wn*32 ..
    if (doDirect) {
        size_t rbase = ((size_t)b * NN + ic * 256 + wm * 64 + g) * NN +
                       (size_t)j * 128 + wn * 32 + 2 * t;
#pragma unroll
        for (int mi = 0; mi < 4; mi++) {
            size_t r0 = rbase + (size_t)(mi * 16) * NN;
#pragma unroll
            for (int ni = 0; ni < 4; ni++) {
                float2 v0 = make_float2(-acc[mi][ni][0], -acc[mi][ni][1]);
                float2 v1 = make_float2(-acc[mi][ni][2], -acc[mi][ni][3]);
                *(float2*)(out + r0 + ni * 8) = v0;
                *(float2*)(out + r0 + (size_t)8 * NN + ni * 8) = v1;
            }
        }
    }

    // stage transposed quadrant into free A buffer (quadrant q -> Aq)
    if (doMirror) {
        float* STGb = (wm >> 1) ? A1 : A0;    // [128 cols][LDT]
        const int cbase = wn * 32 + 2 * t;
        const int rb = (wm & 1) * 64 + g;
#pragma unroll
        for (int mi = 0; mi < 4; mi++) {
            int r = rb + mi * 16;
#pragma unroll
            for (int ni = 0; ni < 4; ni++) {
                int c = cbase + ni * 8;
                STGb[c * LDT + r]           = -acc[mi][ni][0];
                STGb[(c + 1) * LDT + r]     = -acc[mi][ni][1];
                STGb[c * LDT + r + 8]       = -acc[mi][ni][2];
                STGb[(c + 1) * LDT + r + 8] = -acc[mi][ni][3];
            }
        }
    }
    __syncthreads();

    // cooperative mirrored stores: tile (j, ihq) for each quadrant with j > ihq
#pragma unroll
    for (int q = 0; q < 2; q++) {
        const int ihq = 2 * ic + q;
        if (j > ihq) {
            const float* STGb = q ? A1 : A0;
            size_t tbase = ((size_t)b * NN + (size_t)j * 128) * NN + ihq * 128;
#pragma unroll
            for (int it = 0; it < 8; it++) {
                int idx = tid + it * 512;
                int c = idx >> 5, q4 = idx & 31;
                float4 v = *(float4*)&STGb[c * LDT + q4 * 4];
                *(float4*)(out + tbase + (size_t)c * NN + q4 * 4) = v;
            }
        }
    }
}

// ---------------------------------------------------------------------------
extern "C" void kernel_launch(void* const* d_in, const int* in_sizes, int n_in,
                              void* d_out, int out_size) {
    const float* obs        = (const float*)d_in[0];
    const float* gen_number = (const float*)d_in[1];
    const float* W_gen      = (const float*)d_in[2];
    const float* b_gen      = (const float*)d_in[3];
    const float* W_act      = (const float*)d_in[4];
    const float* b_act      = (const float*)d_in[5];
    const float* W_v1       = (const float*)d_in[6];
    const float* b_v1       = (const float*)d_in[7];
    const float* W_v2       = (const float*)d_in[8];
    const float* b_v2       = (const float*)d_in[9];
    float* out = (float*)d_out;

    cudaFuncSetAttribute(hc_kernel, cudaFuncAttributeMaxDynamicSharedMemorySize,
                         HC_SMEM_BYTES);
    cudaFuncSetAttribute(actor_kernel, cudaFuncAttributeMaxDynamicSharedMemorySize,
                         ACT_SMEM_BYTES);

    hc_kernel<<<dim3(NN / 128, BB), 256, HC_SMEM_BYTES>>>(
        obs, gen_number, W_gen, b_gen, W_act, b_act, W_v1, b_v1, W_v2, b_v2);
    actor_kernel<<<dim3(272, BB), 512, ACT_SMEM_BYTES>>>(out, out_size);
}

// round 8
// speedup vs baseline: 1.1010x; 1.1010x over previous
#include <cuda_runtime.h>
#include <math.h>
#include <stdint.h>

#define BB 4
#define NN 4096
#define FF 512
#define HA 128
#define HV 32

// Scratch (device globals: no allocation allowed)
__device__ float g_hn[BB][NN][HA];    // normalized h, row-major, tf32-rounded (8 MB)
__device__ float g_part[BB][32];

// ---------------------------------------------------------------------------
__device__ __forceinline__ float tf32r(float x) {
    uint32_t o;
    asm("cvt.rna.tf32.f32 %0, %1;" : "=r"(o) : "f"(x));
    return __uint_as_float(o);
}

__device__ __forceinline__ uint32_t s2u(const void* p) {
    uint32_t a;
    asm("{ .reg .u64 t; cvta.to.shared.u64 t, %1; cvt.u32.u64 %0, t; }"
        : "=r"(a) : "l"(p));
    return a;
}

__device__ __forceinline__ void cp16(uint32_t dst, const float* src) {
    asm volatile("cp.async.cg.shared.global [%0], [%1], 16;"
                 :: "r"(dst), "l"(src));
}

__device__ __forceinline__ void mma_tf32(float* d, const uint32_t* a,
                                         const uint32_t* b) {
    asm volatile(
        "mma.sync.aligned.m16n8k8.row.col.f32.tf32.tf32.f32 "
        "{%0,%1,%2,%3}, {%4,%5,%6,%7}, {%8,%9}, {%0,%1,%2,%3};"
        : "+f"(d[0]), "+f"(d[1]), "+f"(d[2]), "+f"(d[3])
        : "r"(a[0]), "r"(a[1]), "r"(a[2]), "r"(a[3]), "r"(b[0]), "r"(b[1]));
}

// ---------------------------------------------------------------------------
// FUSED hc kernel (unchanged, proven 32us).
// ---------------------------------------------------------------------------
#define AS0 0
#define AS1 4608            // As: [128][36]
#define BS0 9216
#define BS1 13568           // Bs: [32][136]
#define WS0 17920
#define WS1 19200           // Ws: [32][40]
#define REDO 20480          // [128][8]
#define RINVO 21504         // [128]
#define CREDO 21632         // [128]
#define CWO 21760           // [4]
#define HC_FLOATS 21764
#define HC_SMEM_BYTES (HC_FLOATS * 4)

__global__ __launch_bounds__(256, 1) void hc_kernel(const float* __restrict__ obs,
                                                    const float* __restrict__ gen_number,
                                                    const float* __restrict__ W_gen,
                                                    const float* __restrict__ b_gen,
                                                    const float* __restrict__ W_act,
                                                    const float* __restrict__ b_act,
                                                    const float* __restrict__ W_v1,
                                                    const float* __restrict__ b_v1,
                                                    const float* __restrict__ W_v2,
                                                    const float* __restrict__ b_v2) {
    extern __shared__ float sm[];
    const uint32_t smb = s2u(sm);

    const int b  = blockIdx.y;
    const int m0 = blockIdx.x * 128;
    const int tid = threadIdx.x;
    const int wid = tid >> 5;
    const int lane = tid & 31;
    const int g = lane >> 2;
    const int t = lane & 3;
    const int wm = wid >> 1;
    const int wn = wid & 1;

    const float* obs_b = obs + ((size_t)b * NN + m0) * FF;

    float acc[2][8][4];
    float accv[2][4][4];
#pragma unroll
    for (int mi = 0; mi < 2; mi++) {
#pragma unroll
        for (int ni = 0; ni < 8; ni++)
#pragma unroll
            for (int q = 0; q < 4; q++) acc[mi][ni][q] = 0.f;
#pragma unroll
        for (int ni = 0; ni < 4; ni++)
#pragma unroll
            for (int q = 0; q < 4; q++) accv[mi][ni][q] = 0.f;
    }

    auto issue = [&](int ck, int buf) {
        const int k0 = ck * 32;
        uint32_t as = smb + (uint32_t)((buf ? AS1 : AS0) * 4);
        uint32_t bs = smb + (uint32_t)((buf ? BS1 : BS0) * 4);
        uint32_t ws = smb + (uint32_t)((buf ? WS1 : WS0) * 4);
#pragma unroll
        for (int i = 0; i < 4; i++) {
            int c = tid + i * 256;
            int row = c >> 3, kc = c & 7;
            cp16(as + (uint32_t)(row * 36 + kc * 4) * 4u,
                 obs_b + (size_t)row * FF + k0 + kc * 4);
        }
#pragma unroll
        for (int i = 0; i < 4; i++) {
            int c = tid + i * 256;
            int kk = c >> 5, cg = c & 31;
            cp16(bs + (uint32_t)(kk * 136 + cg * 4) * 4u,
                 W_act + (size_t)(k0 + kk) * HA + cg * 4);
        }
        {
            int kk = tid >> 3, cg = tid & 7;
            cp16(ws + (uint32_t)(kk * 40 + cg * 4) * 4u,
                 W_v1 + (size_t)(k0 + kk) * HV + cg * 4);
        }
    };

    issue(0, 0);
    asm volatile("cp.async.commit_group;" ::: "memory");
    issue(1, 1);
    asm volatile("cp.async.commit_group;" ::: "memory");
    asm volatile("cp.async.wait_group 1;" ::: "memory");
    __syncthreads();

#pragma unroll 1
    for (int ck = 0; ck < 16; ck++) {
        const int buf = ck & 1;
        const float* A  = sm + (buf ? AS1 : AS0) + wm * 32 * 36;
        const float* Bm = sm + (buf ? BS1 : BS0) + wn * 64;
        const float* Wc = sm + (buf ? WS1 : WS0);
#pragma unroll
        for (int ks = 0; ks < 4; ks++) {
            const int kk = ks * 8;
            uint32_t af[2][4];
#pragma unroll
            for (int mi = 0; mi < 2; mi++) {
                const float* ap = A + (mi * 16 + g) * 36 + kk + t;
                af[mi][0] = __float_as_uint(ap[0]);
                af[mi][1] = __float_as_uint(ap[8 * 36]);
                af[mi][2] = __float_as_uint(ap[4]);
                af[mi][3] = __float_as_uint(ap[8 * 36 + 4]);
            }
            uint32_t bf[8][2];
#pragma unroll
            for (int ni = 0; ni < 8; ni++) {
                const float* bp = Bm + (kk + t) * 136 + ni * 8 + g;
                bf[ni][0] = __float_as_uint(bp[0]);
                bf[ni][1] = __float_as_uint(bp[4 * 136]);
            }
#pragma unroll
            for (int mi = 0; mi < 2; mi++)
#pragma unroll
                for (int ni = 0; ni < 8; ni++)
                    mma_tf32(acc[mi][ni], af[mi], bf[ni]);
            if (wn == 0) {
                uint32_t bc[4][2];
#pragma unroll
                for (int ni = 0; ni < 4; ni++) {
                    const float* bp = Wc + (kk + t) * 40 + ni * 8 + g;
                    bc[ni][0] = __float_as_uint(bp[0]);
                    bc[ni][1] = __float_as_uint(bp[4 * 40]);
                }
#pragma unroll
                for (int mi = 0; mi < 2; mi++)
#pragma unroll
                    for (int ni = 0; ni < 4; ni++)
                        mma_tf32(accv[mi][ni], af[mi], bc[ni]);
            }
        }
        __syncthreads();
        if (ck + 2 < 16) issue(ck + 2, buf);
        asm volatile("cp.async.commit_group;" ::: "memory");
        asm volatile("cp.async.wait_group 1;" ::: "memory");
        __syncthreads();
    }

    float gv;
    {
        float x = gen_number[b] * W_gen[0] + b_gen[0];
        gv = (x > 0.f) ? x : 0.01f * x;
    }

#pragma unroll
    for (int ni = 0; ni < 8; ni++) {
        int c0 = wn * 64 + ni * 8 + 2 * t;
        float a0 = fmaf(gv, W_act[(size_t)FF * HA + c0], b_act[c0]);
        float a1 = fmaf(gv, W_act[(size_t)FF * HA + c0 + 1], b_act[c0 + 1]);
#pragma unroll
        for (int mi = 0; mi < 2; mi++) {
            acc[mi][ni][0] += a0; acc[mi][ni][1] += a1;
            acc[mi][ni][2] += a0; acc[mi][ni][3] += a1;
        }
    }

    float* RED = sm + REDO;
#pragma unroll
    for (int mi = 0; mi < 2; mi++)
#pragma unroll
        for (int d = 0; d < 2; d++) {
            float s = 0.f;
#pragma unroll
            for (int ni = 0; ni < 8; ni++) {
                s = fmaf(acc[mi][ni][2 * d], acc[mi][ni][2 * d], s);
                s = fmaf(acc[mi][ni][2 * d + 1], acc[mi][ni][2 * d + 1], s);
            }
            int row = wm * 32 + mi * 16 + g + 8 * d;
            RED[row * 8 + wn * 4 + t] = s;
        }
    __syncthreads();
    float* RINV = sm + RINVO;
    if (tid < 128) {
        float s = 0.f;
#pragma unroll
        for (int x = 0; x < 8; x++) s += RED[tid * 8 + x];
        RINV[tid] = 1.f / fmaxf(sqrtf(s), 1e-8f);
    }
    __syncthreads();

    float* STG = sm;
#pragma unroll
    for (int mi = 0; mi < 2; mi++)
#pragma unroll
        for (int d = 0; d < 2; d++) {
            int row = wm * 32 + mi * 16 + g + 8 * d;
            float iv = RINV[row];
#pragma unroll
            for (int ni = 0; ni < 8; ni++) {
                int col = wn * 64 + ni * 8 + 2 * t;
                STG[row * 132 + col]     = tf32r(acc[mi][ni][2 * d] * iv);
                STG[row * 132 + col + 1] = tf32r(acc[mi][ni][2 * d + 1] * iv);
            }
        }

    float* CRED = sm + CREDO;
    if (wn == 0) {
#pragma unroll
        for (int mi = 0; mi < 2; mi++)
#pragma unroll
            for (int d = 0; d < 2; d++) {
                float cv = 0.f;
#pragma unroll
                for (int ni = 0; ni < 4; ni++) {
#pragma unroll
                    for (int j = 0; j < 2; j++) {
                        int cc = ni * 8 + 2 * t + j;
                        float hvv = accv[mi][ni][2 * d + j] +
                                    fmaf(gv, W_v1[(size_t)FF * HV + cc], b_v1[cc]);
                        hvv = fmaxf(hvv, 0.f);
                        cv = fmaf(hvv, W_v2[cc], cv);
                    }
                }
                cv += __shfl_xor_sync(0xffffffffu, cv, 1);
                cv += __shfl_xor_sync(0xffffffffu, cv, 2);
                if (t == 0) {
                    int row = wm * 32 + mi * 16 + g + 8 * d;
                    CRED[row] = cv + b_v2[0];
                }
            }
    }
    __syncthreads();

#pragma unroll
    for (int i = 0; i < 16; i++) {
        int idx = tid + i * 256;
        int row = idx >> 5, c4 = idx & 31;
        float4 v = *(float4*)&STG[row * 132 + c4 * 4];
        *(float4*)&g_hn[b][m0 + row][c4 * 4] = v;
    }

    float* CW = sm + CWO;
    if (tid < 128) {
        float v = CRED[tid];
#pragma unroll
        for (int off = 16; off > 0; off >>= 1)
            v += __shfl_down_sync(0xffffffffu, v, off);
        if ((tid & 31) == 0) CW[tid >> 5] = v;
    }
    __syncthreads();
    if (tid == 0)
        g_part[b][blockIdx.x] = CW[0] + CW[1] + CW[2] + CW[3];
}

// ---------------------------------------------------------------------------
// Actor v5: small-CTA, 2 CTAs/SM for phase overlap. 256 threads, tile
// 128x128, warp grid 2(m)x4(n), warp tile 64x32. K in 4 chunks of 32,
// cp.async double-buffered: buffers A[128][36] x2 + B[128][36] x2 = 73.7KB.
// Symmetric grid: only j>=i tiles (528/batch); mirror tile staged (transposed)
// through the chunk buffers after compute, then drained coalesced.
// ---------------------------------------------------------------------------
#define CA0 0
#define CA1 4608
#define CB0 9216
#define CB1 13824            // note: 13824 = 3*4608
#define ACT_WORDS 18432      // 4 * 4608
#define ACT_SMEM_BYTES (ACT_WORDS * 4)   // 73728
#define LDT 132              // mirror staging stride (reuses whole buffer area)

__global__ __launch_bounds__(256, 2) void actor_kernel(float* __restrict__ out,
                                                       int out_size) {
    extern __shared__ float smem[];
    const uint32_t smb = s2u(smem);

    const int tid = threadIdx.x;
    const int wid = tid >> 5;
    const int lane = tid & 31;
    const int g = lane >> 2;
    const int t = lane & 3;
    const int wm = wid >> 2;             // 0..1
    const int wn = wid & 3;              // 0..3
    const int b = blockIdx.y;
    const int cid = blockIdx.x;

    // fold critic finalize into one CTA
    if (cid == 0 && b == 0 && tid < BB) {
        float s = 0.f;
#pragma unroll
        for (int k = 0; k < 32; k++) s += g_part[tid][k];
        out[(size_t)out_size - BB + tid] = s * (1.f / NN);
    }

    // decode cid -> (i, j), j >= i, 528 per batch
    int i = 0, j;
    {
        int c = cid, ch;
        while (c >= (ch = 32 - i)) { c -= ch; i++; }
        j = i + c;
    }

    const float* aSrc = &g_hn[b][i * 128][0];
    const float* bSrc = &g_hn[b][j * 128][0];

    // chunk loader: chunk ck (32 k-values) of A and B into buffer buf
    auto issue = [&](int ck, int buf) {
        const int k0 = ck * 32;
        uint32_t as = smb + (uint32_t)((buf ? CA1 : CA0) * 4);
        uint32_t bs = smb + (uint32_t)((buf ? CB1 : CB0) * 4);
#pragma unroll
        for (int it = 0; it < 4; it++) {
            int c = tid + it * 256;
            int row = c >> 3, kc = c & 7;
            cp16(as + (uint32_t)(row * 36 + kc * 4) * 4u,
                 aSrc + (size_t)row * HA + k0 + kc * 4);
        }
#pragma unroll
        for (int it = 0; it < 4; it++) {
            int c = tid + it * 256;
            int row = c >> 3, kc = c & 7;
            cp16(bs + (uint32_t)(row * 36 + kc * 4) * 4u,
                 bSrc + (size_t)row * HA + k0 + kc * 4);
        }
    };

    issue(0, 0);
    asm volatile("cp.async.commit_group;" ::: "memory");
    issue(1, 1);
    asm volatile("cp.async.commit_group;" ::: "memory");
    asm volatile("cp.async.wait_group 1;" ::: "memory");
    __syncthreads();

    float acc[4][4][4];
#pragma unroll
    for (int mi = 0; mi < 4; mi++)
#pragma unroll
        for (int ni = 0; ni < 4; ni++)
#pragma unroll
            for (int q = 0; q < 4; q++) acc[mi][ni][q] = 0.f;

#pragma unroll 1
    for (int ck = 0; ck < 4; ck++) {
        const int buf = ck & 1;
        const float* A = smem + (buf ? CA1 : CA0) + (wm * 64) * 36;
        const float* Bm = smem + (buf ? CB1 : CB0) + (wn * 32) * 36;
#pragma unroll
        for (int ks = 0; ks < 4; ks++) {
            const int kk = ks * 8;
            uint32_t af[4][4];
#pragma unroll
            for (int mi = 0; mi < 4; mi++) {
                const float* ap = A + (mi * 16 + g) * 36 + kk + t;
                af[mi][0] = __float_as_uint(ap[0]);
                af[mi][1] = __float_as_uint(ap[8 * 36]);
                af[mi][2] = __float_as_uint(ap[4]);
                af[mi][3] = __float_as_uint(ap[8 * 36 + 4]);
            }
            uint32_t bf[4][2];
#pragma unroll
            for (int ni = 0; ni < 4; ni++) {
                const float* bp = Bm + (ni * 8 + g) * 36 + kk + t;
                bf[ni][0] = __float_as_uint(bp[0]);
                bf[ni][1] = __float_as_uint(bp[4]);
            }
#pragma unroll
            for (int mi = 0; mi < 4; mi++)
#pragma unroll
                for (int ni = 0; ni < 4; ni++)
                    mma_tf32(acc[mi][ni], af[mi], bf[ni]);
        }
        __syncthreads();
        if (ck + 2 < 4) issue(ck + 2, buf);
        asm volatile("cp.async.commit_group;" ::: "memory");
        asm volatile("cp.async.wait_group 1;" ::: "memory");
        __syncthreads();
    }

    // direct store: tile (i, j), coalesced float2 from registers
    {
        size_t rbase = ((size_t)b * NN + i * 128 + wm * 64 + g) * NN +
                       (size_t)j * 128 + wn * 32 + 2 * t;
#pragma unroll
        for (int mi = 0; mi < 4; mi++) {
            size_t r0 = rbase + (size_t)(mi * 16) * NN;
#pragma unroll
            for (int ni = 0; ni < 4; ni++) {
                float2 v0 = make_float2(-acc[mi][ni][0], -acc[mi][ni][1]);
                float2 v1 = make_float2(-acc[mi][ni][2], -acc[mi][ni][3]);
                *(float2*)(out + r0 + ni * 8) = v0;
                *(float2*)(out + r0 + (size_t)8 * NN + ni * 8) = v1;
            }
        }
    }

    if (j > i) {
        // stage transposed tile into the (now free) chunk buffers: [col][row]
        float* STGb = smem;
        const int cbase = wn * 32 + 2 * t;
        const int rb = wm * 64 + g;
#pragma unroll
        for (int mi = 0; mi < 4; mi++) {
            int r = rb + mi * 16;
#pragma unroll
            for (int ni = 0; ni < 4; ni++) {
                int c = cbase + ni * 8;
                STGb[c * LDT + r]           = -acc[mi][ni][0];
                STGb[(c + 1) * LDT + r]     = -acc[mi][ni][1];
                STGb[c * LDT + r + 8]       = -acc[mi][ni][2];
                STGb[(c + 1) * LDT + r + 8] = -acc[mi][ni][3];
            }
        }
        __syncthreads();
        // mirrored store: tile (j, i), coalesced
        size_t tbase = ((size_t)b * NN + (size_t)j * 128) * NN + (size_t)i * 128;
#pragma unroll
        for (int it = 0; it < 16; it++) {
            int idx = tid + it * 256;
            int c = idx >> 5, q4 = idx & 31;
            float4 v = *(float4*)&STGb[c * LDT + q4 * 4];
            *(float4*)(out + tbase + (size_t)c * NN + q4 * 4) = v;
        }
    }
}

// ---------------------------------------------------------------------------
extern "C" void kernel_launch(void* const* d_in, const int* in_sizes, int n_in,
                              void* d_out, int out_size) {
    const float* obs        = (const float*)d_in[0];
    const float* gen_number = (const float*)d_in[1];
    const float* W_gen      = (const float*)d_in[2];
    const float* b_gen      = (const float*)d_in[3];
    const float* W_act      = (const float*)d_in[4];
    const float* b_act      = (const float*)d_in[5];
    const float* W_v1       = (const float*)d_in[6];
    const float* b_v1       = (const float*)d_in[7];
    const float* W_v2       = (const float*)d_in[8];
    const float* b_v2       = (const float*)d_in[9];
    float* out = (float*)d_out;

    cudaFuncSetAttribute(hc_kernel, cudaFuncAttributeMaxDynamicSharedMemorySize,
                         HC_SMEM_BYTES);
    cudaFuncSetAttribute(actor_kernel, cudaFuncAttributeMaxDynamicSharedMemorySize,
                         ACT_SMEM_BYTES);

    hc_kernel<<<dim3(NN / 128, BB), 256, HC_SMEM_BYTES>>>(
        obs, gen_number, W_gen, b_gen, W_act, b_act, W_v1, b_v1, W_v2, b_v2);
    actor_kernel<<<dim3(528, BB), 256, ACT_SMEM_BYTES>>>(out, out_size);
}

// round 9
// speedup vs baseline: 1.1777x; 1.0697x over previous
#include <cuda_runtime.h>
#include <math.h>
#include <stdint.h>

#define BB 4
#define NN 4096
#define FF 512
#define HA 128
#define HV 32

// Scratch (device globals: no allocation allowed)
__device__ float g_hn[BB][NN][HA];    // normalized h, row-major, tf32-rounded (8 MB)
__device__ float g_part[BB][32];

// ---------------------------------------------------------------------------
__device__ __forceinline__ float tf32r(float x) {
    uint32_t o;
    asm("cvt.rna.tf32.f32 %0, %1;" : "=r"(o) : "f"(x));
    return __uint_as_float(o);
}

__device__ __forceinline__ uint32_t s2u(const void* p) {
    uint32_t a;
    asm("{ .reg .u64 t; cvta.to.shared.u64 t, %1; cvt.u32.u64 %0, t; }"
        : "=r"(a) : "l"(p));
    return a;
}

__device__ __forceinline__ void cp16(uint32_t dst, const float* src) {
    asm volatile("cp.async.cg.shared.global [%0], [%1], 16;"
                 :: "r"(dst), "l"(src));
}

__device__ __forceinline__ void mma_tf32(float* d, const uint32_t* a,
                                         const uint32_t* b) {
    asm volatile(
        "mma.sync.aligned.m16n8k8.row.col.f32.tf32.tf32.f32 "
        "{%0,%1,%2,%3}, {%4,%5,%6,%7}, {%8,%9}, {%0,%1,%2,%3};"
        : "+f"(d[0]), "+f"(d[1]), "+f"(d[2]), "+f"(d[3])
        : "r"(a[0]), "r"(a[1]), "r"(a[2]), "r"(a[3]), "r"(b[0]), "r"(b[1]));
}

// ---------------------------------------------------------------------------
// FUSED hc kernel (unchanged, proven 32us).
// ---------------------------------------------------------------------------
#define AS0 0
#define AS1 4608            // As: [128][36]
#define BS0 9216
#define BS1 13568           // Bs: [32][136]
#define WS0 17920
#define WS1 19200           // Ws: [32][40]
#define REDO 20480          // [128][8]
#define RINVO 21504         // [128]
#define CREDO 21632         // [128]
#define CWO 21760           // [4]
#define HC_FLOATS 21764
#define HC_SMEM_BYTES (HC_FLOATS * 4)

__global__ __launch_bounds__(256, 1) void hc_kernel(const float* __restrict__ obs,
                                                    const float* __restrict__ gen_number,
                                                    const float* __restrict__ W_gen,
                                                    const float* __restrict__ b_gen,
                                                    const float* __restrict__ W_act,
                                                    const float* __restrict__ b_act,
                                                    const float* __restrict__ W_v1,
                                                    const float* __restrict__ b_v1,
                                                    const float* __restrict__ W_v2,
                                                    const float* __restrict__ b_v2) {
    extern __shared__ float sm[];
    const uint32_t smb = s2u(sm);

    const int b  = blockIdx.y;
    const int m0 = blockIdx.x * 128;
    const int tid = threadIdx.x;
    const int wid = tid >> 5;
    const int lane = tid & 31;
    const int g = lane >> 2;
    const int t = lane & 3;
    const int wm = wid >> 1;
    const int wn = wid & 1;

    const float* obs_b = obs + ((size_t)b * NN + m0) * FF;

    float acc[2][8][4];
    float accv[2][4][4];
#pragma unroll
    for (int mi = 0; mi < 2; mi++) {
#pragma unroll
        for (int ni = 0; ni < 8; ni++)
#pragma unroll
            for (int q = 0; q < 4; q++) acc[mi][ni][q] = 0.f;
#pragma unroll
        for (int ni = 0; ni < 4; ni++)
#pragma unroll
            for (int q = 0; q < 4; q++) accv[mi][ni][q] = 0.f;
    }

    auto issue = [&](int ck, int buf) {
        const int k0 = ck * 32;
        uint32_t as = smb + (uint32_t)((buf ? AS1 : AS0) * 4);
        uint32_t bs = smb + (uint32_t)((buf ? BS1 : BS0) * 4);
        uint32_t ws = smb + (uint32_t)((buf ? WS1 : WS0) * 4);
#pragma unroll
        for (int i = 0; i < 4; i++) {
            int c = tid + i * 256;
            int row = c >> 3, kc = c & 7;
            cp16(as + (uint32_t)(row * 36 + kc * 4) * 4u,
                 obs_b + (size_t)row * FF + k0 + kc * 4);
        }
#pragma unroll
        for (int i = 0; i < 4; i++) {
            int c = tid + i * 256;
            int kk = c >> 5, cg = c & 31;
            cp16(bs + (uint32_t)(kk * 136 + cg * 4) * 4u,
                 W_act + (size_t)(k0 + kk) * HA + cg * 4);
        }
        {
            int kk = tid >> 3, cg = tid & 7;
            cp16(ws + (uint32_t)(kk * 40 + cg * 4) * 4u,
                 W_v1 + (size_t)(k0 + kk) * HV + cg * 4);
        }
    };

    issue(0, 0);
    asm volatile("cp.async.commit_group;" ::: "memory");
    issue(1, 1);
    asm volatile("cp.async.commit_group;" ::: "memory");
    asm volatile("cp.async.wait_group 1;" ::: "memory");
    __syncthreads();

#pragma unroll 1
    for (int ck = 0; ck < 16; ck++) {
        const int buf = ck & 1;
        const float* A  = sm + (buf ? AS1 : AS0) + wm * 32 * 36;
        const float* Bm = sm + (buf ? BS1 : BS0) + wn * 64;
        const float* Wc = sm + (buf ? WS1 : WS0);
#pragma unroll
        for (int ks = 0; ks < 4; ks++) {
            const int kk = ks * 8;
            uint32_t af[2][4];
#pragma unroll
            for (int mi = 0; mi < 2; mi++) {
                const float* ap = A + (mi * 16 + g) * 36 + kk + t;
                af[mi][0] = __float_as_uint(ap[0]);
                af[mi][1] = __float_as_uint(ap[8 * 36]);
                af[mi][2] = __float_as_uint(ap[4]);
                af[mi][3] = __float_as_uint(ap[8 * 36 + 4]);
            }
            uint32_t bf[8][2];
#pragma unroll
            for (int ni = 0; ni < 8; ni++) {
                const float* bp = Bm + (kk + t) * 136 + ni * 8 + g;
                bf[ni][0] = __float_as_uint(bp[0]);
                bf[ni][1] = __float_as_uint(bp[4 * 136]);
            }
#pragma unroll
            for (int mi = 0; mi < 2; mi++)
#pragma unroll
                for (int ni = 0; ni < 8; ni++)
                    mma_tf32(acc[mi][ni], af[mi], bf[ni]);
            if (wn == 0) {
                uint32_t bc[4][2];
#pragma unroll
                for (int ni = 0; ni < 4; ni++) {
                    const float* bp = Wc + (kk + t) * 40 + ni * 8 + g;
                    bc[ni][0] = __float_as_uint(bp[0]);
                    bc[ni][1] = __float_as_uint(bp[4 * 40]);
                }
#pragma unroll
                for (int mi = 0; mi < 2; mi++)
#pragma unroll
                    for (int ni = 0; ni < 4; ni++)
                        mma_tf32(accv[mi][ni], af[mi], bc[ni]);
            }
        }
        __syncthreads();
        if (ck + 2 < 16) issue(ck + 2, buf);
        asm volatile("cp.async.commit_group;" ::: "memory");
        asm volatile("cp.async.wait_group 1;" ::: "memory");
        __syncthreads();
    }

    float gv;
    {
        float x = gen_number[b] * W_gen[0] + b_gen[0];
        gv = (x > 0.f) ? x : 0.01f * x;
    }

#pragma unroll
    for (int ni = 0; ni < 8; ni++) {
        int c0 = wn * 64 + ni * 8 + 2 * t;
        float a0 = fmaf(gv, W_act[(size_t)FF * HA + c0], b_act[c0]);
        float a1 = fmaf(gv, W_act[(size_t)FF * HA + c0 + 1], b_act[c0 + 1]);
#pragma unroll
        for (int mi = 0; mi < 2; mi++) {
            acc[mi][ni][0] += a0; acc[mi][ni][1] += a1;
            acc[mi][ni][2] += a0; acc[mi][ni][3] += a1;
        }
    }

    float* RED = sm + REDO;
#pragma unroll
    for (int mi = 0; mi < 2; mi++)
#pragma unroll
        for (int d = 0; d < 2; d++) {
            float s = 0.f;
#pragma unroll
            for (int ni = 0; ni < 8; ni++) {
                s = fmaf(acc[mi][ni][2 * d], acc[mi][ni][2 * d], s);
                s = fmaf(acc[mi][ni][2 * d + 1], acc[mi][ni][2 * d + 1], s);
            }
            int row = wm * 32 + mi * 16 + g + 8 * d;
            RED[row * 8 + wn * 4 + t] = s;
        }
    __syncthreads();
    float* RINV = sm + RINVO;
    if (tid < 128) {
        float s = 0.f;
#pragma unroll
        for (int x = 0; x < 8; x++) s += RED[tid * 8 + x];
        RINV[tid] = 1.f / fmaxf(sqrtf(s), 1e-8f);
    }
    __syncthreads();

    float* STG = sm;
#pragma unroll
    for (int mi = 0; mi < 2; mi++)
#pragma unroll
        for (int d = 0; d < 2; d++) {
            int row = wm * 32 + mi * 16 + g + 8 * d;
            float iv = RINV[row];
#pragma unroll
            for (int ni = 0; ni < 8; ni++) {
                int col = wn * 64 + ni * 8 + 2 * t;
                STG[row * 132 + col]     = tf32r(acc[mi][ni][2 * d] * iv);
                STG[row * 132 + col + 1] = tf32r(acc[mi][ni][2 * d + 1] * iv);
            }
        }

    float* CRED = sm + CREDO;
    if (wn == 0) {
#pragma unroll
        for (int mi = 0; mi < 2; mi++)
#pragma unroll
            for (int d = 0; d < 2; d++) {
                float cv = 0.f;
#pragma unroll
                for (int ni = 0; ni < 4; ni++) {
#pragma unroll
                    for (int j = 0; j < 2; j++) {
                        int cc = ni * 8 + 2 * t + j;
                        float hvv = accv[mi][ni][2 * d + j] +
                                    fmaf(gv, W_v1[(size_t)FF * HV + cc], b_v1[cc]);
                        hvv = fmaxf(hvv, 0.f);
                        cv = fmaf(hvv, W_v2[cc], cv);
                    }
                }
                cv += __shfl_xor_sync(0xffffffffu, cv, 1);
                cv += __shfl_xor_sync(0xffffffffu, cv, 2);
                if (t == 0) {
                    int row = wm * 32 + mi * 16 + g + 8 * d;
                    CRED[row] = cv + b_v2[0];
                }
            }
    }
    __syncthreads();

#pragma unroll
    for (int i = 0; i < 16; i++) {
        int idx = tid + i * 256;
        int row = idx >> 5, c4 = idx & 31;
        float4 v = *(float4*)&STG[row * 132 + c4 * 4];
        *(float4*)&g_hn[b][m0 + row][c4 * 4] = v;
    }

    float* CW = sm + CWO;
    if (tid < 128) {
        float v = CRED[tid];
#pragma unroll
        for (int off = 16; off > 0; off >>= 1)
            v += __shfl_down_sync(0xffffffffu, v, off);
        if ((tid & 31) == 0) CW[tid >> 5] = v;
    }
    __syncthreads();
    if (tid == 0)
        g_part[b][blockIdx.x] = CW[0] + CW[1] + CW[2] + CW[3];
}

// ---------------------------------------------------------------------------
// Actor v6: 128x128 tile, 256 threads, 2 CTAs/SM, 3-stage cp.async pipeline.
// Buffers: A stages s=0..2 at s*4608, B stages at (3+s)*4608 ([128][36] each).
// 110.6KB smem -> 2 CTAs/SM. Chunks of 32 k; prologue issues 3, steady state
// keeps 2 in flight (wait targets chunk issued 2 iterations earlier).
// Symmetric: j>=i tiles only; mirror staged transposed through buffers.
// ---------------------------------------------------------------------------
#define CBUF 4608
#define ACT_WORDS (6 * CBUF)             // 27648
#define ACT_SMEM_BYTES (ACT_WORDS * 4)   // 110592
#define LDT 132                          // mirror staging stride

__global__ __launch_bounds__(256, 2) void actor_kernel(float* __restrict__ out,
                                                       int out_size) {
    extern __shared__ float smem[];
    const uint32_t smb = s2u(smem);

    const int tid = threadIdx.x;
    const int wid = tid >> 5;
    const int lane = tid & 31;
    const int g = lane >> 2;
    const int t = lane & 3;
    const int wm = wid >> 2;             // 0..1
    const int wn = wid & 3;              // 0..3
    const int b = blockIdx.y;
    const int cid = blockIdx.x;

    // fold critic finalize into one CTA
    if (cid == 0 && b == 0 && tid < BB) {
        float s = 0.f;
#pragma unroll
        for (int k = 0; k < 32; k++) s += g_part[tid][k];
        out[(size_t)out_size - BB + tid] = s * (1.f / NN);
    }

    // decode cid -> (i, j), j >= i, 528 per batch
    int i = 0, j;
    {
        int c = cid, ch;
        while (c >= (ch = 32 - i)) { c -= ch; i++; }
        j = i + c;
    }

    const float* aSrc = &g_hn[b][i * 128][0];
    const float* bSrc = &g_hn[b][j * 128][0];

    // chunk loader: chunk ck (32 k-values) of A and B into stage s
    auto issue = [&](int ck, int s) {
        const int k0 = ck * 32;
        uint32_t as = smb + (uint32_t)(s * CBUF * 4);
        uint32_t bs = smb + (uint32_t)((3 + s) * CBUF * 4);
#pragma unroll
        for (int it = 0; it < 4; it++) {
            int c = tid + it * 256;
            int row = c >> 3, kc = c & 7;
            cp16(as + (uint32_t)(row * 36 + kc * 4) * 4u,
                 aSrc + (size_t)row * HA + k0 + kc * 4);
        }
#pragma unroll
        for (int it = 0; it < 4; it++) {
            int c = tid + it * 256;
            int row = c >> 3, kc = c & 7;
            cp16(bs + (uint32_t)(row * 36 + kc * 4) * 4u,
                 bSrc + (size_t)row * HA + k0 + kc * 4);
        }
        asm volatile("cp.async.commit_group;" ::: "memory");
    };

    float acc[4][4][4];
#pragma unroll
    for (int mi = 0; mi < 4; mi++)
#pragma unroll
        for (int ni = 0; ni < 4; ni++)
#pragma unroll
            for (int q = 0; q < 4; q++) acc[mi][ni][q] = 0.f;

    // compute one chunk from stage s
    auto compute = [&](int s) {
        const float* A  = smem + s * CBUF + (wm * 64) * 36;
        const float* Bm = smem + (3 + s) * CBUF + (wn * 32) * 36;
#pragma unroll
        for (int ks = 0; ks < 4; ks++) {
            const int kk = ks * 8;
            uint32_t af[4][4];
#pragma unroll
            for (int mi = 0; mi < 4; mi++) {
                const float* ap = A + (mi * 16 + g) * 36 + kk + t;
                af[mi][0] = __float_as_uint(ap[0]);
                af[mi][1] = __float_as_uint(ap[8 * 36]);
                af[mi][2] = __float_as_uint(ap[4]);
                af[mi][3] = __float_as_uint(ap[8 * 36 + 4]);
            }
            uint32_t bf[4][2];
#pragma unroll
            for (int ni = 0; ni < 4; ni++) {
                const float* bp = Bm + (ni * 8 + g) * 36 + kk + t;
                bf[ni][0] = __float_as_uint(bp[0]);
                bf[ni][1] = __float_as_uint(bp[4]);
            }
#pragma unroll
            for (int mi = 0; mi < 4; mi++)
#pragma unroll
                for (int ni = 0; ni < 4; ni++)
                    mma_tf32(acc[mi][ni], af[mi], bf[ni]);
        }
    };

    // 3-deep prologue: chunks 0,1,2 in flight before first compute
    issue(0, 0);
    issue(1, 1);
    issue(2, 2);
    asm volatile("cp.async.wait_group 2;" ::: "memory");   // chunk 0 ready
    __syncthreads();

    compute(0);
    __syncthreads();                                       // stage 0 free
    issue(3, 0);
    asm volatile("cp.async.wait_group 2;" ::: "memory");   // chunk 1 ready
    __syncthreads();

    compute(1);
    asm volatile("cp.async.wait_group 1;" ::: "memory");   // chunk 2 ready
    __syncthreads();

    compute(2);
    asm volatile("cp.async.wait_group 0;" ::: "memory");   // chunk 3 ready
    __syncthreads();

    compute(0);                                            // chunk 3 in stage 0

    // direct store: tile (i, j), coalesced float2 from registers
    {
        size_t rbase = ((size_t)b * NN + i * 128 + wm * 64 + g) * NN +
                       (size_t)j * 128 + wn * 32 + 2 * t;
#pragma unroll
        for (int mi = 0; mi < 4; mi++) {
            size_t r0 = rbase + (size_t)(mi * 16) * NN;
#pragma unroll
            for (int ni = 0; ni < 4; ni++) {
                float2 v0 = make_float2(-acc[mi][ni][0], -acc[mi][ni][1]);
                float2 v1 = make_float2(-acc[mi][ni][2], -acc[mi][ni][3]);
                *(float2*)(out + r0 + ni * 8) = v0;
                *(float2*)(out + r0 + (size_t)8 * NN + ni * 8) = v1;
            }
        }
    }

    if (j > i) {
        __syncthreads();      // everyone done reading stage buffers
        // stage transposed tile into the (now free) buffers: [col][row]
        float* STGb = smem;
        const int cbase = wn * 32 + 2 * t;
        const int rb = wm * 64 + g;
#pragma unroll
        for (int mi = 0; mi < 4; mi++) {
            int r = rb + mi * 16;
#pragma unroll
            for (int ni = 0; ni < 4; ni++) {
                int c = cbase + ni * 8;
                STGb[c * LDT + r]           = -acc[mi][ni][0];
                STGb[(c + 1) * LDT + r]     = -acc[mi][ni][1];
                STGb[c * LDT + r + 8]       = -acc[mi][ni][2];
                STGb[(c + 1) * LDT + r + 8] = -acc[mi][ni][3];
            }
        }
        __syncthreads();
        // mirrored store: tile (j, i), coalesced
        size_t tbase = ((size_t)b * NN + (size_t)j * 128) * NN + (size_t)i * 128;
#pragma unroll
        for (int it = 0; it < 16; it++) {
            int idx = tid + it * 256;
            int c = idx >> 5, q4 = idx & 31;
            float4 v = *(float4*)&STGb[c * LDT + q4 * 4];
            *(float4*)(out + tbase + (size_t)c * NN + q4 * 4) = v;
        }
    }
}

// ---------------------------------------------------------------------------
extern "C" void kernel_launch(void* const* d_in, const int* in_sizes, int n_in,
                              void* d_out, int out_size) {
    const float* obs        = (const float*)d_in[0];
    const float* gen_number = (const float*)d_in[1];
    const float* W_gen      = (const float*)d_in[2];
    const float* b_gen      = (const float*)d_in[3];
    const float* W_act      = (const float*)d_in[4];
    const float* b_act      = (const float*)d_in[5];
    const float* W_v1       = (const float*)d_in[6];
    const float* b_v1       = (const float*)d_in[7];
    const float* W_v2       = (const float*)d_in[8];
    const float* b_v2       = (const float*)d_in[9];
    float* out = (float*)d_out;

    cudaFuncSetAttribute(hc_kernel, cudaFuncAttributeMaxDynamicSharedMemorySize,
                         HC_SMEM_BYTES);
    cudaFuncSetAttribute(actor_kernel, cudaFuncAttributeMaxDynamicSharedMemorySize,
                         ACT_SMEM_BYTES);

    hc_kernel<<<dim3(NN / 128, BB), 256, HC_SMEM_BYTES>>>(
        obs, gen_number, W_gen, b_gen, W_act, b_act, W_v1, b_v1, W_v2, b_v2);
    actor_kernel<<<dim3(528, BB), 256, ACT_SMEM_BYTES>>>(out, out_size);
}